// round 15
// baseline (speedup 1.0000x reference)
#include <cuda_runtime.h>
#include <cuda_fp16.h>
#include <float.h>
#include <stdint.h>

// Problem constants
#define BB 4
#define NN 1024
#define HH 16
#define DH 64
#define INNER 1024
#define BH 64          // B*H
#define MM 4096        // B*N
#define KDIM 1024
#define SCALE 0.125f

// ---------------------------------------------------------------------------
// Scratch: fp16 split-2 planes on A-side operands, single fp16 on B-side.
// x, ao: [m][k] hi/lo. Weights: [k][n] single. q: hi/lo; k,v: single.
// ---------------------------------------------------------------------------
__device__ __half g_xhi[(size_t)MM * KDIM],  g_xlo[(size_t)MM * KDIM];
__device__ __half g_wq[(size_t)KDIM * 1024];
__device__ __half g_wkv[(size_t)KDIM * 2048];
__device__ __half g_wo[(size_t)KDIM * 1024];
__device__ __half g_qhi[(size_t)BH * NN * DH], g_qlo[(size_t)BH * NN * DH];
__device__ __half g_k[(size_t)BH * NN * DH];
__device__ __half g_v[(size_t)BH * NN * DH];
__device__ __half g_aohi[(size_t)MM * INNER], g_aolo[(size_t)MM * INNER];

// ---------------------------------------------------------------------------
// Helpers
// ---------------------------------------------------------------------------
__device__ __forceinline__ void mma_f16(float* c, const unsigned* a,
                                        unsigned b0, unsigned b1) {
    asm volatile(
        "mma.sync.aligned.m16n8k16.row.col.f32.f16.f16.f32 "
        "{%0,%1,%2,%3}, {%4,%5,%6,%7}, {%8,%9}, {%0,%1,%2,%3};\n"
        : "+f"(c[0]), "+f"(c[1]), "+f"(c[2]), "+f"(c[3])
        : "r"(a[0]), "r"(a[1]), "r"(a[2]), "r"(a[3]), "r"(b0), "r"(b1));
}
__device__ __forceinline__ unsigned su32(const void* p) {
    return (unsigned)__cvta_generic_to_shared(p);
}
__device__ __forceinline__ void ldsm4(unsigned& r0, unsigned& r1, unsigned& r2,
                                      unsigned& r3, unsigned a) {
    asm volatile("ldmatrix.sync.aligned.m8n8.x4.shared.b16 {%0,%1,%2,%3},[%4];"
                 : "=r"(r0), "=r"(r1), "=r"(r2), "=r"(r3) : "r"(a));
}
__device__ __forceinline__ void ldsm4t(unsigned& r0, unsigned& r1, unsigned& r2,
                                       unsigned& r3, unsigned a) {
    asm volatile("ldmatrix.sync.aligned.m8n8.x4.trans.shared.b16 {%0,%1,%2,%3},[%4];"
                 : "=r"(r0), "=r"(r1), "=r"(r2), "=r"(r3) : "r"(a));
}
#define CPA16(dst, src) \
    asm volatile("cp.async.cg.shared.global [%0],[%1],16;\n" ::"r"(dst), "l"(src))
#define CP_COMMIT asm volatile("cp.async.commit_group;\n")
#define CP_WAIT0 asm volatile("cp.async.wait_group 0;\n")
#define CP_WAIT1 asm volatile("cp.async.wait_group 1;\n")

__device__ __forceinline__ void split_f16(float v, __half& hi, __half& lo) {
    hi = __float2half_rn(v);
    lo = __float2half_rn(v - __half2float(hi));
}
__device__ __forceinline__ unsigned pack2h(__half a, __half b) {
    __half2 h = __halves2half2(a, b);
    return *(unsigned*)&h;
}

// ---------------------------------------------------------------------------
// Fused convert (one launch): x -> hi/lo; Wq/Wkv/Wo -> single fp16.
// ---------------------------------------------------------------------------
#define X4   (MM * KDIM / 4)
#define WQ4  (KDIM * 1024 / 4)
#define WKV4 (KDIM * 2048 / 4)
#define WO4  (KDIM * 1024 / 4)
#define TOT4 (X4 + WQ4 + WKV4 + WO4)

__global__ __launch_bounds__(256) void convert_all(
    const float* __restrict__ x, const float* __restrict__ Wq,
    const float* __restrict__ Wkv, const float* __restrict__ Wo)
{
    int i = blockIdx.x * blockDim.x + threadIdx.x;
    if (i >= TOT4) return;
    if (i < X4) {
        float4 v = ((const float4*)x)[i];
        __half h[4], l[4];
        split_f16(v.x, h[0], l[0]); split_f16(v.y, h[1], l[1]);
        split_f16(v.z, h[2], l[2]); split_f16(v.w, h[3], l[3]);
        ((ushort4*)g_xhi)[i] = make_ushort4(*(unsigned short*)&h[0], *(unsigned short*)&h[1],
                                            *(unsigned short*)&h[2], *(unsigned short*)&h[3]);
        ((ushort4*)g_xlo)[i] = make_ushort4(*(unsigned short*)&l[0], *(unsigned short*)&l[1],
                                            *(unsigned short*)&l[2], *(unsigned short*)&l[3]);
        return;
    }
    int j = i - X4;
    const float* src;
    __half* dst;
    if (j < WQ4)                { src = Wq;  dst = g_wq; }
    else if ((j -= WQ4) < WKV4) { src = Wkv; dst = g_wkv; }
    else                        { j -= WKV4; src = Wo; dst = g_wo; }
    float4 v = ((const float4*)src)[j];
    __half h[4] = { __float2half_rn(v.x), __float2half_rn(v.y),
                    __float2half_rn(v.z), __float2half_rn(v.w) };
    ((ushort4*)dst)[j] = make_ushort4(*(unsigned short*)&h[0], *(unsigned short*)&h[1],
                                      *(unsigned short*)&h[2], *(unsigned short*)&h[3]);
}

// ---------------------------------------------------------------------------
// fp16 split-2 GEMM: BK=32, 3-stage cp.async (85.5KB smem, 2 CTA/SM),
// term-major ordering. Per-acc order identical to R14 -> same numerics.
// mode 0: fused QKV; mode 2: g_ao @ Wo + bias.
// ---------------------------------------------------------------------------
#define GEMM_SMEM (3 * 2 * 128 * 40 * 2 + 3 * 32 * 136 * 2)

__device__ __forceinline__ void gemm_store(int m, int c, float v, int mode,
                                           const float* __restrict__ bias,
                                           float* __restrict__ outp) {
    if (mode == 2) { outp[(size_t)m * 1024 + c] = v + bias[c]; return; }
    int bb = m >> 10, n = m & 1023;
    int ci = c;
    if (c < 1024) {
        int h = ci >> 6, d = ci & 63;
        size_t idx = (((size_t)(bb * 16 + h)) * 1024 + n) * 64 + d;
        __half hi, lo;
        split_f16(v, hi, lo);
        g_qhi[idx] = hi; g_qlo[idx] = lo;
    } else {
        __half* dst = (c < 2048) ? g_k : g_v;
        ci = (c < 2048) ? c - 1024 : c - 2048;
        int h = ci >> 6, d = ci & 63;
        size_t idx = (((size_t)(bb * 16 + h)) * 1024 + n) * 64 + d;
        dst[idx] = __float2half_rn(v);
    }
}

__global__ __launch_bounds__(256, 2) void mma_gemm(
    const float* __restrict__ bias, float* __restrict__ outp, int mode)
{
    extern __shared__ __half smg[];
    __half* Asb = smg;                       // [st][pl][128][40]
    __half* Bsb = smg + 3 * 2 * 128 * 40;    // [st][32][136]
#define ASADDR(st, pl, r, c) (Asb + ((((st) * 2 + (pl)) * 128 + (r)) * 40) + (c))
#define BSADDR(st, r, c) (Bsb + (((st) * 32 + (r)) * 136) + (c))

    const int tid = threadIdx.x;
    const int warp = tid >> 5, lane = tid & 31;
    const int wm = (warp & 3) * 32, wn = (warp >> 2) * 64;
    const int g = lane >> 2, t4 = lane & 3;
    const int bm = blockIdx.y * 128, bn = blockIdx.x * 128;

    const __half *ahi, *alo, *w;
    int strideW, bnl;
    if (mode == 2)        { ahi = g_aohi; alo = g_aolo; w = g_wo;  strideW = 1024; bnl = bn; }
    else if (bn < 1024)   { ahi = g_xhi;  alo = g_xlo;  w = g_wq;  strideW = 1024; bnl = bn; }
    else                  { ahi = g_xhi;  alo = g_xlo;  w = g_wkv; strideW = 2048; bnl = bn - 1024; }

    float acc[2][8][4];
#pragma unroll
    for (int mi = 0; mi < 2; mi++)
#pragma unroll
        for (int ni = 0; ni < 8; ni++)
#pragma unroll
            for (int r = 0; r < 4; r++) acc[mi][ni][r] = 0.f;

    const int ar = tid >> 1, ac = (tid & 1) * 16;
    const int br = tid >> 3, bc = (tid & 7) * 16;

    auto stage_load = [&](int st, int k0) {
        const __half* a0 = ahi + (size_t)(bm + ar) * KDIM + k0 + ac;
        const __half* a1 = alo + (size_t)(bm + ar) * KDIM + k0 + ac;
        const __half* wb = w + (size_t)(k0 + br) * strideW + bnl + bc;
        CPA16(su32(ASADDR(st, 0, ar, ac)),     a0);
        CPA16(su32(ASADDR(st, 0, ar, ac + 8)), a0 + 8);
        CPA16(su32(ASADDR(st, 1, ar, ac)),     a1);
        CPA16(su32(ASADDR(st, 1, ar, ac + 8)), a1 + 8);
        CPA16(su32(BSADDR(st, br, bc)),        wb);
        CPA16(su32(BSADDR(st, br, bc + 8)),    wb + 8);
        CP_COMMIT;
    };

    stage_load(0, 0);
    stage_load(1, 32);

    const int NIT = KDIM / 32;      // 32
    int st = 0;
    for (int it = 0; it < NIT; it++) {
        if (it + 1 < NIT) { CP_WAIT1; } else { CP_WAIT0; }
        __syncthreads();
        if (it + 2 < NIT) {
            int nst = st + 2; if (nst >= 3) nst -= 3;
            stage_load(nst, (it + 2) * 32);
        }

#pragma unroll
        for (int ks = 0; ks < 32; ks += 16) {
            unsigned fa_hi[2][4], fa_lo[2][4];
#pragma unroll
            for (int mi = 0; mi < 2; mi++) {
                int row = wm + mi * 16 + (lane & 15);
                int col = ks + (lane >> 4) * 8;
                ldsm4(fa_hi[mi][0], fa_hi[mi][1], fa_hi[mi][2], fa_hi[mi][3],
                      su32(ASADDR(st, 0, row, col)));
                ldsm4(fa_lo[mi][0], fa_lo[mi][1], fa_lo[mi][2], fa_lo[mi][3],
                      su32(ASADDR(st, 1, row, col)));
            }
#pragma unroll
            for (int nqp = 0; nqp < 2; nqp++) {
                unsigned fb[2][4];
#pragma unroll
                for (int q = 0; q < 2; q++) {
                    int nq = nqp * 2 + q;
                    int row = ks + (lane & 15);
                    int col = wn + nq * 16 + (lane >> 4) * 8;
                    ldsm4t(fb[q][0], fb[q][1], fb[q][2], fb[q][3],
                           su32(BSADDR(st, row, col)));
                }
                // pass 1: Ahi * B
#pragma unroll
                for (int q = 0; q < 2; q++)
#pragma unroll
                    for (int mi = 0; mi < 2; mi++) {
                        int ni = (nqp * 2 + q) * 2;
                        mma_f16(acc[mi][ni],     fa_hi[mi], fb[q][0], fb[q][1]);
                        mma_f16(acc[mi][ni + 1], fa_hi[mi], fb[q][2], fb[q][3]);
                    }
                // pass 2: Alo * B
#pragma unroll
                for (int q = 0; q < 2; q++)
#pragma unroll
                    for (int mi = 0; mi < 2; mi++) {
                        int ni = (nqp * 2 + q) * 2;
                        mma_f16(acc[mi][ni],     fa_lo[mi], fb[q][0], fb[q][1]);
                        mma_f16(acc[mi][ni + 1], fa_lo[mi], fb[q][2], fb[q][3]);
                    }
            }
        }
        if (++st >= 3) st = 0;
    }

#pragma unroll
    for (int mi = 0; mi < 2; mi++)
#pragma unroll
        for (int ni = 0; ni < 8; ni++) {
            int row = bm + wm + mi * 16 + g;
            int col = bn + wn + ni * 8 + t4 * 2;
            gemm_store(row,     col,     acc[mi][ni][0], mode, bias, outp);
            gemm_store(row,     col + 1, acc[mi][ni][1], mode, bias, outp);
            gemm_store(row + 8, col,     acc[mi][ni][2], mode, bias, outp);
            gemm_store(row + 8, col + 1, acc[mi][ni][3], mode, bias, outp);
        }
#undef ASADDR
#undef BSADDR
}

// ---------------------------------------------------------------------------
// Flash attention: Q split-2, K/V single, P single fp16 (NEW: PV 1 MMA/frag).
// Double-buffered K/V, 37KB smem, 3 CTA/SM. Structure R9/R14-proven.
// ---------------------------------------------------------------------------
#define ATTN_SMEM (2 * 2 * 64 * 72 * 2 + 2 * 64 * 4)

__global__ __launch_bounds__(128, 3) void attn_kernel(
    const float* __restrict__ rel, const int* __restrict__ qmask,
    const int* __restrict__ cmask)
{
    extern __shared__ char sma[];
    __half* KVb = (__half*)sma;                 // [st][reg(K/V)][64][72]
    float* cmb = (float*)(sma + 2 * 2 * 64 * 72 * 2);
#define KVADDR(st, rg, r, c) (KVb + ((((st) * 2 + (rg)) * 64 + (r)) * 72) + (c))

    const int bh = blockIdx.y;
    const int q0 = blockIdx.x * 64;
    const int b = bh >> 4, h = bh & 15;
    const int tid = threadIdx.x;
    const int wq = tid >> 5, lane = tid & 31;
    const int g = lane >> 2, t4 = lane & 3;

    // ---- Q prologue ----
    {
        const __half* qh = g_qhi + ((size_t)bh * NN + q0) * DH;
        const __half* ql = g_qlo + ((size_t)bh * NN + q0) * DH;
#pragma unroll
        for (int i = 0; i < 4; i++) {
            int c = tid + 128 * i;
            int r = c >> 3, cc = (c & 7) * 8;
            CPA16(su32(KVADDR(0, 0, r, cc)), qh + (size_t)r * DH + cc);
            CPA16(su32(KVADDR(0, 1, r, cc)), ql + (size_t)r * DH + cc);
        }
        CP_COMMIT; CP_WAIT0;
    }
    __syncthreads();

    unsigned aq_hi[4][4], aq_lo[4][4];
#pragma unroll
    for (int ks = 0; ks < 4; ks++) {
        int row = wq * 16 + (lane & 15);
        int col = ks * 16 + (lane >> 4) * 8;
        ldsm4(aq_hi[ks][0], aq_hi[ks][1], aq_hi[ks][2], aq_hi[ks][3],
              su32(KVADDR(0, 0, row, col)));
        ldsm4(aq_lo[ks][0], aq_lo[ks][1], aq_lo[ks][2], aq_lo[ks][3],
              su32(KVADDR(0, 1, row, col)));
    }
    __syncthreads();

    auto load_kv = [&](int st, int j0) {
        const __half* kk = g_k + ((size_t)bh * NN + j0) * DH;
        const __half* vv = g_v + ((size_t)bh * NN + j0) * DH;
#pragma unroll
        for (int i = 0; i < 4; i++) {
            int c = tid + 128 * i;
            int r = c >> 3, cc = (c & 7) * 8;
            CPA16(su32(KVADDR(st, 0, r, cc)), kk + (size_t)r * DH + cc);
            CPA16(su32(KVADDR(st, 1, r, cc)), vv + (size_t)r * DH + cc);
        }
        if (tid < 64) cmb[st * 64 + tid] = (cmask[b * NN + j0 + tid] != 0) ? 1.f : 0.f;
        CP_COMMIT;
    };

    load_kv(0, 0);

    const int row0 = q0 + wq * 16 + g;
    const float qm0 = (qmask[b * NN + row0] != 0) ? 1.f : 0.f;
    const float qm1 = (qmask[b * NN + row0 + 8] != 0) ? 1.f : 0.f;
    const float* relr0 = rel + ((size_t)bh * NN + row0) * NN;
    const float* relr1 = relr0 + (size_t)8 * NN;

    float m0 = -FLT_MAX, m1 = -FLT_MAX, l0 = 0.f, l1 = 0.f;
    float acc_o[8][4];
#pragma unroll
    for (int i = 0; i < 8; i++)
#pragma unroll
        for (int r = 0; r < 4; r++) acc_o[i][r] = 0.f;

    for (int it = 0; it < NN / 64; it++) {
        const int st = it & 1;
        const int j0 = it * 64;

        CP_WAIT0;
        __syncthreads();
        if (it + 1 < NN / 64) load_kv(st ^ 1, j0 + 64);

        // ---- S = Q K^T (split-2: Qhi*K, Qlo*K) ----
        float s[8][4];
#pragma unroll
        for (int ni = 0; ni < 8; ni++)
#pragma unroll
            for (int r = 0; r < 4; r++) s[ni][r] = 0.f;

#pragma unroll
        for (int ks = 0; ks < 4; ks++) {
#pragma unroll
            for (int nq = 0; nq < 4; nq++) {
                int row = nq * 16 + ((lane & 16) >> 1) + (lane & 7);
                int col = ks * 16 + (lane & 8);
                unsigned k0e, k1e, k0o, k1o;
                ldsm4(k0e, k1e, k0o, k1o, su32(KVADDR(st, 0, row, col)));
                mma_f16(s[nq * 2],     aq_hi[ks], k0e, k1e);
                mma_f16(s[nq * 2],     aq_lo[ks], k0e, k1e);
                mma_f16(s[nq * 2 + 1], aq_hi[ks], k0o, k1o);
                mma_f16(s[nq * 2 + 1], aq_lo[ks], k0o, k1o);
            }
        }

        // ---- bias + mask (inline loads, proven) ----
#pragma unroll
        for (int ni = 0; ni < 8; ni++) {
            int col = ni * 8 + t4 * 2;
            float2 ra = *(const float2*)(relr0 + j0 + col);
            float2 rb = *(const float2*)(relr1 + j0 + col);
            float c0 = cmb[st * 64 + col], c1 = cmb[st * 64 + col + 1];
            s[ni][0] = (c0 * qm0 != 0.f) ? s[ni][0] * SCALE + ra.x : -FLT_MAX;
            s[ni][1] = (c1 * qm0 != 0.f) ? s[ni][1] * SCALE + ra.y : -FLT_MAX;
            s[ni][2] = (c0 * qm1 != 0.f) ? s[ni][2] * SCALE + rb.x : -FLT_MAX;
            s[ni][3] = (c1 * qm1 != 0.f) ? s[ni][3] * SCALE + rb.y : -FLT_MAX;
        }

        // ---- online softmax (proven) ----
        float mx0 = -FLT_MAX, mx1 = -FLT_MAX;
#pragma unroll
        for (int ni = 0; ni < 8; ni++) {
            mx0 = fmaxf(mx0, fmaxf(s[ni][0], s[ni][1]));
            mx1 = fmaxf(mx1, fmaxf(s[ni][2], s[ni][3]));
        }
        mx0 = fmaxf(mx0, __shfl_xor_sync(0xffffffffu, mx0, 1));
        mx0 = fmaxf(mx0, __shfl_xor_sync(0xffffffffu, mx0, 2));
        mx1 = fmaxf(mx1, __shfl_xor_sync(0xffffffffu, mx1, 1));
        mx1 = fmaxf(mx1, __shfl_xor_sync(0xffffffffu, mx1, 2));

        float mn0 = fmaxf(m0, mx0), mn1 = fmaxf(m1, mx1);
        float al0 = __expf(m0 - mn0), al1 = __expf(m1 - mn1);
        float sum0 = 0.f, sum1 = 0.f;
#pragma unroll
        for (int ni = 0; ni < 8; ni++) {
            s[ni][0] = __expf(s[ni][0] - mn0);
            s[ni][1] = __expf(s[ni][1] - mn0);
            s[ni][2] = __expf(s[ni][2] - mn1);
            s[ni][3] = __expf(s[ni][3] - mn1);
            sum0 += s[ni][0] + s[ni][1];
            sum1 += s[ni][2] + s[ni][3];
        }
        sum0 += __shfl_xor_sync(0xffffffffu, sum0, 1);
        sum0 += __shfl_xor_sync(0xffffffffu, sum0, 2);
        sum1 += __shfl_xor_sync(0xffffffffu, sum1, 1);
        sum1 += __shfl_xor_sync(0xffffffffu, sum1, 2);
        l0 = l0 * al0 + sum0; m0 = mn0;
        l1 = l1 * al1 + sum1; m1 = mn1;
#pragma unroll
        for (int i = 0; i < 8; i++) {
            acc_o[i][0] *= al0; acc_o[i][1] *= al0;
            acc_o[i][2] *= al1; acc_o[i][3] *= al1;
        }

        // ---- P single-fp16 repack + PV (1 MMA per fragment) ----
#pragma unroll
        for (int kc = 0; kc < 4; kc++) {
            unsigned ap[4] = {
                pack2h(__float2half_rn(s[kc * 2][0]),     __float2half_rn(s[kc * 2][1])),
                pack2h(__float2half_rn(s[kc * 2][2]),     __float2half_rn(s[kc * 2][3])),
                pack2h(__float2half_rn(s[kc * 2 + 1][0]), __float2half_rn(s[kc * 2 + 1][1])),
                pack2h(__float2half_rn(s[kc * 2 + 1][2]), __float2half_rn(s[kc * 2 + 1][3]))
            };
#pragma unroll
            for (int nd = 0; nd < 4; nd++) {
                int row = kc * 16 + (lane & 15);
                int col = nd * 16 + (lane >> 4) * 8;
                unsigned v0e, v1e, v0o, v1o;
                ldsm4t(v0e, v1e, v0o, v1o, su32(KVADDR(st, 1, row, col)));
                mma_f16(acc_o[nd * 2],     ap, v0e, v1e);
                mma_f16(acc_o[nd * 2 + 1], ap, v0o, v1o);
            }
        }
    }

    // ---- epilogue -> g_ao fp16 hi/lo planes ----
    float inv0 = 1.f / l0, inv1 = 1.f / l1;
    int r0g = q0 + wq * 16 + g;
#pragma unroll
    for (int nd = 0; nd < 8; nd++) {
        int d = nd * 8 + t4 * 2;
        size_t i0 = (((size_t)b * NN + r0g) * HH + h) * DH + d;
        size_t i1 = (((size_t)b * NN + r0g + 8) * HH + h) * DH + d;
        __half hi, lo;
        split_f16(acc_o[nd][0] * inv0, hi, lo); g_aohi[i0] = hi;     g_aolo[i0] = lo;
        split_f16(acc_o[nd][1] * inv0, hi, lo); g_aohi[i0 + 1] = hi; g_aolo[i0 + 1] = lo;
        split_f16(acc_o[nd][2] * inv1, hi, lo); g_aohi[i1] = hi;     g_aolo[i1] = lo;
        split_f16(acc_o[nd][3] * inv1, hi, lo); g_aohi[i1 + 1] = hi; g_aolo[i1 + 1] = lo;
    }
#undef KVADDR
}

// ---------------------------------------------------------------------------
// Launch. Inputs: x, rel_pos, query_mask, context_mask, Wq, Wkv, Wo, bo
// ---------------------------------------------------------------------------
extern "C" void kernel_launch(void* const* d_in, const int* in_sizes, int n_in,
                              void* d_out, int out_size) {
    const float* x    = (const float*)d_in[0];
    const float* rel  = (const float*)d_in[1];
    const int*   qmsk = (const int*)d_in[2];
    const int*   cmsk = (const int*)d_in[3];
    const float* Wq   = (const float*)d_in[4];
    const float* Wkv  = (const float*)d_in[5];
    const float* Wo   = (const float*)d_in[6];
    const float* bo   = (const float*)d_in[7];
    float* out = (float*)d_out;

    cudaFuncSetAttribute(mma_gemm, cudaFuncAttributeMaxDynamicSharedMemorySize,
                         GEMM_SMEM);
    cudaFuncSetAttribute(attn_kernel, cudaFuncAttributeMaxDynamicSharedMemorySize,
                         ATTN_SMEM);

    // fused conversion (one launch)
    convert_all<<<(TOT4 + 255) / 256, 256>>>(x, Wq, Wkv, Wo);
    // fused Q+K+V projection: 3072 cols x 4096 rows
    mma_gemm<<<dim3(24, 32), 256, GEMM_SMEM>>>(nullptr, nullptr, 0);
    // attention
    attn_kernel<<<dim3(NN / 64, BH), 128, ATTN_SMEM>>>(rel, qmsk, cmsk);
    // output projection + bias
    mma_gemm<<<dim3(8, 32), 256, GEMM_SMEM>>>(bo, out, 2);
}

// round 16
// speedup vs baseline: 1.1004x; 1.1004x over previous
#include <cuda_runtime.h>
#include <cuda_fp16.h>
#include <float.h>
#include <stdint.h>

// Problem constants
#define BB 4
#define NN 1024
#define HH 16
#define DH 64
#define INNER 1024
#define BH 64          // B*H
#define MM 4096        // B*N
#define KDIM 1024
#define SCALE 0.125f

// ---------------------------------------------------------------------------
// Scratch: fp16 split-2 planes on A-side operands, single fp16 on B-side.
// x, ao: [m][k] hi/lo. Weights: [k][n] single. q: hi/lo; k,v: single.
// ---------------------------------------------------------------------------
__device__ __half g_xhi[(size_t)MM * KDIM],  g_xlo[(size_t)MM * KDIM];
__device__ __half g_wq[(size_t)KDIM * 1024];
__device__ __half g_wkv[(size_t)KDIM * 2048];
__device__ __half g_wo[(size_t)KDIM * 1024];
__device__ __half g_qhi[(size_t)BH * NN * DH], g_qlo[(size_t)BH * NN * DH];
__device__ __half g_k[(size_t)BH * NN * DH];
__device__ __half g_v[(size_t)BH * NN * DH];
__device__ __half g_aohi[(size_t)MM * INNER], g_aolo[(size_t)MM * INNER];

// ---------------------------------------------------------------------------
// Helpers
// ---------------------------------------------------------------------------
__device__ __forceinline__ void mma_f16(float* c, const unsigned* a,
                                        unsigned b0, unsigned b1) {
    asm volatile(
        "mma.sync.aligned.m16n8k16.row.col.f32.f16.f16.f32 "
        "{%0,%1,%2,%3}, {%4,%5,%6,%7}, {%8,%9}, {%0,%1,%2,%3};\n"
        : "+f"(c[0]), "+f"(c[1]), "+f"(c[2]), "+f"(c[3])
        : "r"(a[0]), "r"(a[1]), "r"(a[2]), "r"(a[3]), "r"(b0), "r"(b1));
}
__device__ __forceinline__ unsigned su32(const void* p) {
    return (unsigned)__cvta_generic_to_shared(p);
}
__device__ __forceinline__ void ldsm4(unsigned& r0, unsigned& r1, unsigned& r2,
                                      unsigned& r3, unsigned a) {
    asm volatile("ldmatrix.sync.aligned.m8n8.x4.shared.b16 {%0,%1,%2,%3},[%4];"
                 : "=r"(r0), "=r"(r1), "=r"(r2), "=r"(r3) : "r"(a));
}
__device__ __forceinline__ void ldsm4t(unsigned& r0, unsigned& r1, unsigned& r2,
                                       unsigned& r3, unsigned a) {
    asm volatile("ldmatrix.sync.aligned.m8n8.x4.trans.shared.b16 {%0,%1,%2,%3},[%4];"
                 : "=r"(r0), "=r"(r1), "=r"(r2), "=r"(r3) : "r"(a));
}
#define CPA16(dst, src) \
    asm volatile("cp.async.cg.shared.global [%0],[%1],16;\n" ::"r"(dst), "l"(src))
#define CP_COMMIT asm volatile("cp.async.commit_group;\n")
#define CP_WAIT0 asm volatile("cp.async.wait_group 0;\n")
#define CP_WAIT1 asm volatile("cp.async.wait_group 1;\n")

__device__ __forceinline__ void split_f16(float v, __half& hi, __half& lo) {
    hi = __float2half_rn(v);
    lo = __float2half_rn(v - __half2float(hi));
}
__device__ __forceinline__ unsigned pack2h(__half a, __half b) {
    __half2 h = __halves2half2(a, b);
    return *(unsigned*)&h;
}

// ---------------------------------------------------------------------------
// Fused convert (one launch): x -> hi/lo; Wq/Wkv/Wo -> single fp16.
// ---------------------------------------------------------------------------
#define X4   (MM * KDIM / 4)
#define WQ4  (KDIM * 1024 / 4)
#define WKV4 (KDIM * 2048 / 4)
#define WO4  (KDIM * 1024 / 4)
#define TOT4 (X4 + WQ4 + WKV4 + WO4)

__global__ __launch_bounds__(256) void convert_all(
    const float* __restrict__ x, const float* __restrict__ Wq,
    const float* __restrict__ Wkv, const float* __restrict__ Wo)
{
    int i = blockIdx.x * blockDim.x + threadIdx.x;
    if (i >= TOT4) return;
    if (i < X4) {
        float4 v = ((const float4*)x)[i];
        __half h[4], l[4];
        split_f16(v.x, h[0], l[0]); split_f16(v.y, h[1], l[1]);
        split_f16(v.z, h[2], l[2]); split_f16(v.w, h[3], l[3]);
        ((ushort4*)g_xhi)[i] = make_ushort4(*(unsigned short*)&h[0], *(unsigned short*)&h[1],
                                            *(unsigned short*)&h[2], *(unsigned short*)&h[3]);
        ((ushort4*)g_xlo)[i] = make_ushort4(*(unsigned short*)&l[0], *(unsigned short*)&l[1],
                                            *(unsigned short*)&l[2], *(unsigned short*)&l[3]);
        return;
    }
    int j = i - X4;
    const float* src;
    __half* dst;
    if (j < WQ4)                { src = Wq;  dst = g_wq; }
    else if ((j -= WQ4) < WKV4) { src = Wkv; dst = g_wkv; }
    else                        { j -= WKV4; src = Wo; dst = g_wo; }
    float4 v = ((const float4*)src)[j];
    __half h[4] = { __float2half_rn(v.x), __float2half_rn(v.y),
                    __float2half_rn(v.z), __float2half_rn(v.w) };
    ((ushort4*)dst)[j] = make_ushort4(*(unsigned short*)&h[0], *(unsigned short*)&h[1],
                                      *(unsigned short*)&h[2], *(unsigned short*)&h[3]);
}

// ---------------------------------------------------------------------------
// fp16 split-2 GEMM: EXACT R14 config (BK=16, 3-stage cp.async, 49KB smem,
// 2 CTA/SM, term-major ordering). BK=32 confirmed slower 3x — do not retry.
// mode 0: fused QKV; mode 2: g_ao @ Wo + bias.
// ---------------------------------------------------------------------------
#define GEMM_SMEM ((3 * 2 * 128 * 24 + 3 * 16 * 136) * 2)

__device__ __forceinline__ void gemm_store(int m, int c, float v, int mode,
                                           const float* __restrict__ bias,
                                           float* __restrict__ outp) {
    if (mode == 2) { outp[(size_t)m * 1024 + c] = v + bias[c]; return; }
    int bb = m >> 10, n = m & 1023;
    int ci = c;
    if (c < 1024) {
        int h = ci >> 6, d = ci & 63;
        size_t idx = (((size_t)(bb * 16 + h)) * 1024 + n) * 64 + d;
        __half hi, lo;
        split_f16(v, hi, lo);
        g_qhi[idx] = hi; g_qlo[idx] = lo;
    } else {
        __half* dst = (c < 2048) ? g_k : g_v;
        ci = (c < 2048) ? c - 1024 : c - 2048;
        int h = ci >> 6, d = ci & 63;
        size_t idx = (((size_t)(bb * 16 + h)) * 1024 + n) * 64 + d;
        dst[idx] = __float2half_rn(v);
    }
}

__global__ __launch_bounds__(256, 2) void mma_gemm(
    const float* __restrict__ bias, float* __restrict__ outp, int mode)
{
    extern __shared__ __half smg[];
    __half* Asb = smg;                       // [st][pl][128][24]
    __half* Bsb = smg + 3 * 2 * 128 * 24;    // [st][16][136]
#define ASADDR(st, pl, r, c) (Asb + ((((st) * 2 + (pl)) * 128 + (r)) * 24) + (c))
#define BSADDR(st, r, c) (Bsb + (((st) * 16 + (r)) * 136) + (c))

    const int tid = threadIdx.x;
    const int warp = tid >> 5, lane = tid & 31;
    const int wm = (warp & 3) * 32, wn = (warp >> 2) * 64;
    const int g = lane >> 2, t4 = lane & 3;
    const int bm = blockIdx.y * 128, bn = blockIdx.x * 128;

    const __half *ahi, *alo, *w;
    int strideW, bnl;
    if (mode == 2)        { ahi = g_aohi; alo = g_aolo; w = g_wo;  strideW = 1024; bnl = bn; }
    else if (bn < 1024)   { ahi = g_xhi;  alo = g_xlo;  w = g_wq;  strideW = 1024; bnl = bn; }
    else                  { ahi = g_xhi;  alo = g_xlo;  w = g_wkv; strideW = 2048; bnl = bn - 1024; }

    float acc[2][8][4];
#pragma unroll
    for (int mi = 0; mi < 2; mi++)
#pragma unroll
        for (int ni = 0; ni < 8; ni++)
#pragma unroll
            for (int r = 0; r < 4; r++) acc[mi][ni][r] = 0.f;

    const int ar = tid >> 1, ac = (tid & 1) * 8;
    const int br = tid >> 4, bc = (tid & 15) * 8;

    auto stage_load = [&](int st, int k0) {
        CPA16(su32(ASADDR(st, 0, ar, ac)), ahi + (size_t)(bm + ar) * KDIM + k0 + ac);
        CPA16(su32(ASADDR(st, 1, ar, ac)), alo + (size_t)(bm + ar) * KDIM + k0 + ac);
        CPA16(su32(BSADDR(st, br, bc)), w + (size_t)(k0 + br) * strideW + bnl + bc);
        CP_COMMIT;
    };

    stage_load(0, 0);
    stage_load(1, 16);

    const int NIT = KDIM / 16;      // 64
    int st = 0;
    for (int it = 0; it < NIT; it++) {
        if (it + 1 < NIT) { CP_WAIT1; } else { CP_WAIT0; }
        __syncthreads();
        if (it + 2 < NIT) {
            int nst = st + 2; if (nst >= 3) nst -= 3;
            stage_load(nst, (it + 2) * 16);
        }

        unsigned fa_hi[2][4], fa_lo[2][4];
#pragma unroll
        for (int mi = 0; mi < 2; mi++) {
            int row = wm + mi * 16 + (lane & 15);
            int col = (lane >> 4) * 8;
            ldsm4(fa_hi[mi][0], fa_hi[mi][1], fa_hi[mi][2], fa_hi[mi][3],
                  su32(ASADDR(st, 0, row, col)));
            ldsm4(fa_lo[mi][0], fa_lo[mi][1], fa_lo[mi][2], fa_lo[mi][3],
                  su32(ASADDR(st, 1, row, col)));
        }

        // term-major over nq-pairs (R13/R14-proven)
#pragma unroll
        for (int nqp = 0; nqp < 2; nqp++) {
            unsigned fb[2][4];
#pragma unroll
            for (int q = 0; q < 2; q++) {
                int nq = nqp * 2 + q;
                int row = lane & 15;
                int col = wn + nq * 16 + (lane >> 4) * 8;
                ldsm4t(fb[q][0], fb[q][1], fb[q][2], fb[q][3],
                       su32(BSADDR(st, row, col)));
            }
            // pass 1: Ahi * B
#pragma unroll
            for (int q = 0; q < 2; q++)
#pragma unroll
                for (int mi = 0; mi < 2; mi++) {
                    int ni = (nqp * 2 + q) * 2;
                    mma_f16(acc[mi][ni],     fa_hi[mi], fb[q][0], fb[q][1]);
                    mma_f16(acc[mi][ni + 1], fa_hi[mi], fb[q][2], fb[q][3]);
                }
            // pass 2: Alo * B
#pragma unroll
            for (int q = 0; q < 2; q++)
#pragma unroll
                for (int mi = 0; mi < 2; mi++) {
                    int ni = (nqp * 2 + q) * 2;
                    mma_f16(acc[mi][ni],     fa_lo[mi], fb[q][0], fb[q][1]);
                    mma_f16(acc[mi][ni + 1], fa_lo[mi], fb[q][2], fb[q][3]);
                }
        }
        if (++st >= 3) st = 0;
    }

#pragma unroll
    for (int mi = 0; mi < 2; mi++)
#pragma unroll
        for (int ni = 0; ni < 8; ni++) {
            int row = bm + wm + mi * 16 + g;
            int col = bn + wn + ni * 8 + t4 * 2;
            gemm_store(row,     col,     acc[mi][ni][0], mode, bias, outp);
            gemm_store(row,     col + 1, acc[mi][ni][1], mode, bias, outp);
            gemm_store(row + 8, col,     acc[mi][ni][2], mode, bias, outp);
            gemm_store(row + 8, col + 1, acc[mi][ni][3], mode, bias, outp);
        }
#undef ASADDR
#undef BSADDR
}

// ---------------------------------------------------------------------------
// Flash attention: EXACT R15 config (Q split-2, K/V single, P single fp16,
// double-buffered K/V, 37KB smem, 3 CTA/SM) — measured ~30µs faster than R14.
// ---------------------------------------------------------------------------
#define ATTN_SMEM (2 * 2 * 64 * 72 * 2 + 2 * 64 * 4)

__global__ __launch_bounds__(128, 3) void attn_kernel(
    const float* __restrict__ rel, const int* __restrict__ qmask,
    const int* __restrict__ cmask)
{
    extern __shared__ char sma[];
    __half* KVb = (__half*)sma;                 // [st][reg(K/V)][64][72]
    float* cmb = (float*)(sma + 2 * 2 * 64 * 72 * 2);
#define KVADDR(st, rg, r, c) (KVb + ((((st) * 2 + (rg)) * 64 + (r)) * 72) + (c))

    const int bh = blockIdx.y;
    const int q0 = blockIdx.x * 64;
    const int b = bh >> 4, h = bh & 15;
    const int tid = threadIdx.x;
    const int wq = tid >> 5, lane = tid & 31;
    const int g = lane >> 2, t4 = lane & 3;

    // ---- Q prologue ----
    {
        const __half* qh = g_qhi + ((size_t)bh * NN + q0) * DH;
        const __half* ql = g_qlo + ((size_t)bh * NN + q0) * DH;
#pragma unroll
        for (int i = 0; i < 4; i++) {
            int c = tid + 128 * i;
            int r = c >> 3, cc = (c & 7) * 8;
            CPA16(su32(KVADDR(0, 0, r, cc)), qh + (size_t)r * DH + cc);
            CPA16(su32(KVADDR(0, 1, r, cc)), ql + (size_t)r * DH + cc);
        }
        CP_COMMIT; CP_WAIT0;
    }
    __syncthreads();

    unsigned aq_hi[4][4], aq_lo[4][4];
#pragma unroll
    for (int ks = 0; ks < 4; ks++) {
        int row = wq * 16 + (lane & 15);
        int col = ks * 16 + (lane >> 4) * 8;
        ldsm4(aq_hi[ks][0], aq_hi[ks][1], aq_hi[ks][2], aq_hi[ks][3],
              su32(KVADDR(0, 0, row, col)));
        ldsm4(aq_lo[ks][0], aq_lo[ks][1], aq_lo[ks][2], aq_lo[ks][3],
              su32(KVADDR(0, 1, row, col)));
    }
    __syncthreads();

    auto load_kv = [&](int st, int j0) {
        const __half* kk = g_k + ((size_t)bh * NN + j0) * DH;
        const __half* vv = g_v + ((size_t)bh * NN + j0) * DH;
#pragma unroll
        for (int i = 0; i < 4; i++) {
            int c = tid + 128 * i;
            int r = c >> 3, cc = (c & 7) * 8;
            CPA16(su32(KVADDR(st, 0, r, cc)), kk + (size_t)r * DH + cc);
            CPA16(su32(KVADDR(st, 1, r, cc)), vv + (size_t)r * DH + cc);
        }
        if (tid < 64) cmb[st * 64 + tid] = (cmask[b * NN + j0 + tid] != 0) ? 1.f : 0.f;
        CP_COMMIT;
    };

    load_kv(0, 0);

    const int row0 = q0 + wq * 16 + g;
    const float qm0 = (qmask[b * NN + row0] != 0) ? 1.f : 0.f;
    const float qm1 = (qmask[b * NN + row0 + 8] != 0) ? 1.f : 0.f;
    const float* relr0 = rel + ((size_t)bh * NN + row0) * NN;
    const float* relr1 = relr0 + (size_t)8 * NN;

    float m0 = -FLT_MAX, m1 = -FLT_MAX, l0 = 0.f, l1 = 0.f;
    float acc_o[8][4];
#pragma unroll
    for (int i = 0; i < 8; i++)
#pragma unroll
        for (int r = 0; r < 4; r++) acc_o[i][r] = 0.f;

    for (int it = 0; it < NN / 64; it++) {
        const int st = it & 1;
        const int j0 = it * 64;

        CP_WAIT0;
        __syncthreads();
        if (it + 1 < NN / 64) load_kv(st ^ 1, j0 + 64);

        // ---- S = Q K^T (split-2: Qhi*K, Qlo*K) ----
        float s[8][4];
#pragma unroll
        for (int ni = 0; ni < 8; ni++)
#pragma unroll
            for (int r = 0; r < 4; r++) s[ni][r] = 0.f;

#pragma unroll
        for (int ks = 0; ks < 4; ks++) {
#pragma unroll
            for (int nq = 0; nq < 4; nq++) {
                int row = nq * 16 + ((lane & 16) >> 1) + (lane & 7);
                int col = ks * 16 + (lane & 8);
                unsigned k0e, k1e, k0o, k1o;
                ldsm4(k0e, k1e, k0o, k1o, su32(KVADDR(st, 0, row, col)));
                mma_f16(s[nq * 2],     aq_hi[ks], k0e, k1e);
                mma_f16(s[nq * 2],     aq_lo[ks], k0e, k1e);
                mma_f16(s[nq * 2 + 1], aq_hi[ks], k0o, k1o);
                mma_f16(s[nq * 2 + 1], aq_lo[ks], k0o, k1o);
            }
        }

        // ---- bias + mask (inline loads, proven) ----
#pragma unroll
        for (int ni = 0; ni < 8; ni++) {
            int col = ni * 8 + t4 * 2;
            float2 ra = *(const float2*)(relr0 + j0 + col);
            float2 rb = *(const float2*)(relr1 + j0 + col);
            float c0 = cmb[st * 64 + col], c1 = cmb[st * 64 + col + 1];
            s[ni][0] = (c0 * qm0 != 0.f) ? s[ni][0] * SCALE + ra.x : -FLT_MAX;
            s[ni][1] = (c1 * qm0 != 0.f) ? s[ni][1] * SCALE + ra.y : -FLT_MAX;
            s[ni][2] = (c0 * qm1 != 0.f) ? s[ni][2] * SCALE + rb.x : -FLT_MAX;
            s[ni][3] = (c1 * qm1 != 0.f) ? s[ni][3] * SCALE + rb.y : -FLT_MAX;
        }

        // ---- online softmax (proven) ----
        float mx0 = -FLT_MAX, mx1 = -FLT_MAX;
#pragma unroll
        for (int ni = 0; ni < 8; ni++) {
            mx0 = fmaxf(mx0, fmaxf(s[ni][0], s[ni][1]));
            mx1 = fmaxf(mx1, fmaxf(s[ni][2], s[ni][3]));
        }
        mx0 = fmaxf(mx0, __shfl_xor_sync(0xffffffffu, mx0, 1));
        mx0 = fmaxf(mx0, __shfl_xor_sync(0xffffffffu, mx0, 2));
        mx1 = fmaxf(mx1, __shfl_xor_sync(0xffffffffu, mx1, 1));
        mx1 = fmaxf(mx1, __shfl_xor_sync(0xffffffffu, mx1, 2));

        float mn0 = fmaxf(m0, mx0), mn1 = fmaxf(m1, mx1);
        float al0 = __expf(m0 - mn0), al1 = __expf(m1 - mn1);
        float sum0 = 0.f, sum1 = 0.f;
#pragma unroll
        for (int ni = 0; ni < 8; ni++) {
            s[ni][0] = __expf(s[ni][0] - mn0);
            s[ni][1] = __expf(s[ni][1] - mn0);
            s[ni][2] = __expf(s[ni][2] - mn1);
            s[ni][3] = __expf(s[ni][3] - mn1);
            sum0 += s[ni][0] + s[ni][1];
            sum1 += s[ni][2] + s[ni][3];
        }
        sum0 += __shfl_xor_sync(0xffffffffu, sum0, 1);
        sum0 += __shfl_xor_sync(0xffffffffu, sum0, 2);
        sum1 += __shfl_xor_sync(0xffffffffu, sum1, 1);
        sum1 += __shfl_xor_sync(0xffffffffu, sum1, 2);
        l0 = l0 * al0 + sum0; m0 = mn0;
        l1 = l1 * al1 + sum1; m1 = mn1;
#pragma unroll
        for (int i = 0; i < 8; i++) {
            acc_o[i][0] *= al0; acc_o[i][1] *= al0;
            acc_o[i][2] *= al1; acc_o[i][3] *= al1;
        }

        // ---- P single-fp16 repack + PV (1 MMA per fragment) ----
#pragma unroll
        for (int kc = 0; kc < 4; kc++) {
            unsigned ap[4] = {
                pack2h(__float2half_rn(s[kc * 2][0]),     __float2half_rn(s[kc * 2][1])),
                pack2h(__float2half_rn(s[kc * 2][2]),     __float2half_rn(s[kc * 2][3])),
                pack2h(__float2half_rn(s[kc * 2 + 1][0]), __float2half_rn(s[kc * 2 + 1][1])),
                pack2h(__float2half_rn(s[kc * 2 + 1][2]), __float2half_rn(s[kc * 2 + 1][3]))
            };
#pragma unroll
            for (int nd = 0; nd < 4; nd++) {
                int row = kc * 16 + (lane & 15);
                int col = nd * 16 + (lane >> 4) * 8;
                unsigned v0e, v1e, v0o, v1o;
                ldsm4t(v0e, v1e, v0o, v1o, su32(KVADDR(st, 1, row, col)));
                mma_f16(acc_o[nd * 2],     ap, v0e, v1e);
                mma_f16(acc_o[nd * 2 + 1], ap, v0o, v1o);
            }
        }
    }

    // ---- epilogue -> g_ao fp16 hi/lo planes ----
    float inv0 = 1.f / l0, inv1 = 1.f / l1;
    int r0g = q0 + wq * 16 + g;
#pragma unroll
    for (int nd = 0; nd < 8; nd++) {
        int d = nd * 8 + t4 * 2;
        size_t i0 = (((size_t)b * NN + r0g) * HH + h) * DH + d;
        size_t i1 = (((size_t)b * NN + r0g + 8) * HH + h) * DH + d;
        __half hi, lo;
        split_f16(acc_o[nd][0] * inv0, hi, lo); g_aohi[i0] = hi;     g_aolo[i0] = lo;
        split_f16(acc_o[nd][1] * inv0, hi, lo); g_aohi[i0 + 1] = hi; g_aolo[i0 + 1] = lo;
        split_f16(acc_o[nd][2] * inv1, hi, lo); g_aohi[i1] = hi;     g_aolo[i1] = lo;
        split_f16(acc_o[nd][3] * inv1, hi, lo); g_aohi[i1 + 1] = hi; g_aolo[i1 + 1] = lo;
    }
#undef KVADDR
}

// ---------------------------------------------------------------------------
// Launch. Inputs: x, rel_pos, query_mask, context_mask, Wq, Wkv, Wo, bo
// ---------------------------------------------------------------------------
extern "C" void kernel_launch(void* const* d_in, const int* in_sizes, int n_in,
                              void* d_out, int out_size) {
    const float* x    = (const float*)d_in[0];
    const float* rel  = (const float*)d_in[1];
    const int*   qmsk = (const int*)d_in[2];
    const int*   cmsk = (const int*)d_in[3];
    const float* Wq   = (const float*)d_in[4];
    const float* Wkv  = (const float*)d_in[5];
    const float* Wo   = (const float*)d_in[6];
    const float* bo   = (const float*)d_in[7];
    float* out = (float*)d_out;

    cudaFuncSetAttribute(mma_gemm, cudaFuncAttributeMaxDynamicSharedMemorySize,
                         GEMM_SMEM);
    cudaFuncSetAttribute(attn_kernel, cudaFuncAttributeMaxDynamicSharedMemorySize,
                         ATTN_SMEM);

    // fused conversion (one launch)
    convert_all<<<(TOT4 + 255) / 256, 256>>>(x, Wq, Wkv, Wo);
    // fused Q+K+V projection: 3072 cols x 4096 rows
    mma_gemm<<<dim3(24, 32), 256, GEMM_SMEM>>>(nullptr, nullptr, 0);
    // attention
    attn_kernel<<<dim3(NN / 64, BH), 128, ATTN_SMEM>>>(rel, qmsk, cmsk);
    // output projection + bias
    mma_gemm<<<dim3(8, 32), 256, GEMM_SMEM>>>(bo, out, 2);
}